// round 2
// baseline (speedup 1.0000x reference)
#include <cuda_runtime.h>

// CharRNN: 3-layer tanh RNN, B=512, T=1024, HID=100, VOCAB=62.
// Strategy: batch rows are independent through the recurrence -> partition
// batch over CTAs, fuse all 3 layers + decoder per timestep, weights in smem.
// Layer-1 input projection precomputed per-vocab-token (62x100 table).

#define BB    512
#define TT    1024
#define HID   100
#define VOCAB 62
#define NL    3
#define ROWS  4                 // batch rows per CTA
#define NCTA  (BB / ROWS)       // 128
#define NTHR  128

// ---- shared memory layout (floats) ----
#define OFF_WH1  0              // 100x100
#define OFF_WI2  10000
#define OFF_WH2  20000
#define OFF_WI3  30000
#define OFF_WH3  40000
#define OFF_WDEC 50000          // 62x100
#define OFF_B2   56200          // 100
#define OFF_B3   56300          // 100
#define OFF_BDEC 56400          // 62 (pad to 56464)
#define OFF_H1   56464          // 4x100
#define OFF_H2   56864
#define OFF_H3   57264
#define SMEM_FLOATS 57664       // 230,656 bytes

__device__ float g_table[VOCAB * HID];  // emb@Wi1^T + b_ih1 + b_hh1, per token

// ---------------------------------------------------------------------------
// Prologue: table[v][j] = b_ih[0][j] + b_hh[0][j] + sum_k emb[v][k]*W_ih[0][j][k]
// ---------------------------------------------------------------------------
__global__ void table_kernel(const float* __restrict__ emb,
                             const float* __restrict__ W_ih,
                             const float* __restrict__ b_ih,
                             const float* __restrict__ b_hh) {
    int v = blockIdx.x;
    int j = threadIdx.x;
    if (j >= HID) return;
    float acc = b_ih[j] + b_hh[j];
    const float* e = emb + v * HID;
    const float* w = W_ih + j * HID;
#pragma unroll
    for (int k = 0; k < HID; k++) acc += e[k] * w[k];
    g_table[v * HID + j] = acc;
}

// ---------------------------------------------------------------------------
// Main fused RNN kernel: one CTA handles 4 batch rows for all T steps.
// ---------------------------------------------------------------------------
__global__ __launch_bounds__(NTHR, 1)
void rnn_kernel(const int*   __restrict__ ids,
                const float* __restrict__ W_ih,
                const float* __restrict__ W_hh,
                const float* __restrict__ b_ih,
                const float* __restrict__ b_hh,
                const float* __restrict__ W_dec,
                const float* __restrict__ b_dec,
                float* __restrict__ logits,
                float* __restrict__ hidden) {
    extern __shared__ float s[];
    const int tid = threadIdx.x;
    const int b0  = blockIdx.x * ROWS;

    // ---- stage weights into smem ----
    for (int i = tid; i < HID * HID; i += NTHR) {
        s[OFF_WH1 + i] = W_hh[i];
        s[OFF_WI2 + i] = W_ih[1 * HID * HID + i];
        s[OFF_WH2 + i] = W_hh[1 * HID * HID + i];
        s[OFF_WI3 + i] = W_ih[2 * HID * HID + i];
        s[OFF_WH3 + i] = W_hh[2 * HID * HID + i];
    }
    for (int i = tid; i < VOCAB * HID; i += NTHR) s[OFF_WDEC + i] = W_dec[i];
    if (tid < HID) {
        s[OFF_B2 + tid] = b_ih[1 * HID + tid] + b_hh[1 * HID + tid];
        s[OFF_B3 + tid] = b_ih[2 * HID + tid] + b_hh[2 * HID + tid];
    }
    if (tid < VOCAB) s[OFF_BDEC + tid] = b_dec[tid];
    for (int i = tid; i < ROWS * HID; i += NTHR) {
        s[OFF_H1 + i] = 0.0f;
        s[OFF_H2 + i] = 0.0f;
        s[OFF_H3 + i] = 0.0f;
    }
    __syncthreads();

    const int j = tid;
    const float4* wh1 = reinterpret_cast<const float4*>(s + OFF_WH1 + j * HID);
    const float4* wi2 = reinterpret_cast<const float4*>(s + OFF_WI2 + j * HID);
    const float4* wh2 = reinterpret_cast<const float4*>(s + OFF_WH2 + j * HID);
    const float4* wi3 = reinterpret_cast<const float4*>(s + OFF_WI3 + j * HID);
    const float4* wh3 = reinterpret_cast<const float4*>(s + OFF_WH3 + j * HID);
    const float4* wdc = reinterpret_cast<const float4*>(s + OFF_WDEC + j * HID);
    const float4* h1v[ROWS];
    const float4* h2v[ROWS];
    const float4* h3v[ROWS];
#pragma unroll
    for (int r = 0; r < ROWS; r++) {
        h1v[r] = reinterpret_cast<const float4*>(s + OFF_H1 + r * HID);
        h2v[r] = reinterpret_cast<const float4*>(s + OFF_H2 + r * HID);
        h3v[r] = reinterpret_cast<const float4*>(s + OFF_H3 + r * HID);
    }

    for (int t = 0; t < TT; t++) {
        // ---- prefetch layer-1 input (token table) ----
        float tbl[ROWS];
        if (j < HID) {
#pragma unroll
            for (int r = 0; r < ROWS; r++) {
                int tok = ids[(b0 + r) * TT + t];
                tbl[r] = g_table[tok * HID + j];
            }
        }

        // ---- layer 1: h1 = tanh(table + h1 @ Wh1^T) ----
        float a0 = 0.f, a1 = 0.f, a2 = 0.f, a3 = 0.f;
        if (j < HID) {
#pragma unroll
            for (int kc = 0; kc < HID / 4; kc++) {
                float4 w = wh1[kc];
                float4 x;
                x = h1v[0][kc]; a0 += w.x*x.x + w.y*x.y + w.z*x.z + w.w*x.w;
                x = h1v[1][kc]; a1 += w.x*x.x + w.y*x.y + w.z*x.z + w.w*x.w;
                x = h1v[2][kc]; a2 += w.x*x.x + w.y*x.y + w.z*x.z + w.w*x.w;
                x = h1v[3][kc]; a3 += w.x*x.x + w.y*x.y + w.z*x.z + w.w*x.w;
            }
        }
        __syncthreads();
        if (j < HID) {
            s[OFF_H1 + 0 * HID + j] = tanhf(tbl[0] + a0);
            s[OFF_H1 + 1 * HID + j] = tanhf(tbl[1] + a1);
            s[OFF_H1 + 2 * HID + j] = tanhf(tbl[2] + a2);
            s[OFF_H1 + 3 * HID + j] = tanhf(tbl[3] + a3);
        }
        __syncthreads();

        // ---- layer 2: h2 = tanh(b2 + h1 @ Wi2^T + h2 @ Wh2^T) ----
        a0 = a1 = a2 = a3 = 0.f;
        if (j < HID) {
#pragma unroll
            for (int kc = 0; kc < HID / 4; kc++) {
                float4 wa = wi2[kc];
                float4 wb = wh2[kc];
                float4 x, h;
                x = h1v[0][kc]; h = h2v[0][kc];
                a0 += wa.x*x.x + wa.y*x.y + wa.z*x.z + wa.w*x.w
                    + wb.x*h.x + wb.y*h.y + wb.z*h.z + wb.w*h.w;
                x = h1v[1][kc]; h = h2v[1][kc];
                a1 += wa.x*x.x + wa.y*x.y + wa.z*x.z + wa.w*x.w
                    + wb.x*h.x + wb.y*h.y + wb.z*h.z + wb.w*h.w;
                x = h1v[2][kc]; h = h2v[2][kc];
                a2 += wa.x*x.x + wa.y*x.y + wa.z*x.z + wa.w*x.w
                    + wb.x*h.x + wb.y*h.y + wb.z*h.z + wb.w*h.w;
                x = h1v[3][kc]; h = h2v[3][kc];
                a3 += wa.x*x.x + wa.y*x.y + wa.z*x.z + wa.w*x.w
                    + wb.x*h.x + wb.y*h.y + wb.z*h.z + wb.w*h.w;
            }
        }
        __syncthreads();
        if (j < HID) {
            float b = s[OFF_B2 + j];
            s[OFF_H2 + 0 * HID + j] = tanhf(b + a0);
            s[OFF_H2 + 1 * HID + j] = tanhf(b + a1);
            s[OFF_H2 + 2 * HID + j] = tanhf(b + a2);
            s[OFF_H2 + 3 * HID + j] = tanhf(b + a3);
        }
        __syncthreads();

        // ---- layer 3: h3 = tanh(b3 + h2 @ Wi3^T + h3 @ Wh3^T) ----
        a0 = a1 = a2 = a3 = 0.f;
        if (j < HID) {
#pragma unroll
            for (int kc = 0; kc < HID / 4; kc++) {
                float4 wa = wi3[kc];
                float4 wb = wh3[kc];
                float4 x, h;
                x = h2v[0][kc]; h = h3v[0][kc];
                a0 += wa.x*x.x + wa.y*x.y + wa.z*x.z + wa.w*x.w
                    + wb.x*h.x + wb.y*h.y + wb.z*h.z + wb.w*h.w;
                x = h2v[1][kc]; h = h3v[1][kc];
                a1 += wa.x*x.x + wa.y*x.y + wa.z*x.z + wa.w*x.w
                    + wb.x*h.x + wb.y*h.y + wb.z*h.z + wb.w*h.w;
                x = h2v[2][kc]; h = h3v[2][kc];
                a2 += wa.x*x.x + wa.y*x.y + wa.z*x.z + wa.w*x.w
                    + wb.x*h.x + wb.y*h.y + wb.z*h.z + wb.w*h.w;
                x = h2v[3][kc]; h = h3v[3][kc];
                a3 += wa.x*x.x + wa.y*x.y + wa.z*x.z + wa.w*x.w
                    + wb.x*h.x + wb.y*h.y + wb.z*h.z + wb.w*h.w;
            }
        }
        __syncthreads();
        if (j < HID) {
            float b = s[OFF_B3 + j];
            s[OFF_H3 + 0 * HID + j] = tanhf(b + a0);
            s[OFF_H3 + 1 * HID + j] = tanhf(b + a1);
            s[OFF_H3 + 2 * HID + j] = tanhf(b + a2);
            s[OFF_H3 + 3 * HID + j] = tanhf(b + a3);
        }
        __syncthreads();

        // ---- decoder: logits = b_dec + h3 @ Wdec^T ----
        if (j < VOCAB) {
            float d0, d1, d2, d3;
            d0 = d1 = d2 = d3 = s[OFF_BDEC + j];
#pragma unroll
            for (int kc = 0; kc < HID / 4; kc++) {
                float4 w = wdc[kc];
                float4 x;
                x = h3v[0][kc]; d0 += w.x*x.x + w.y*x.y + w.z*x.z + w.w*x.w;
                x = h3v[1][kc]; d1 += w.x*x.x + w.y*x.y + w.z*x.z + w.w*x.w;
                x = h3v[2][kc]; d2 += w.x*x.x + w.y*x.y + w.z*x.z + w.w*x.w;
                x = h3v[3][kc]; d3 += w.x*x.x + w.y*x.y + w.z*x.z + w.w*x.w;
            }
            logits[((size_t)(b0 + 0) * TT + t) * VOCAB + j] = d0;
            logits[((size_t)(b0 + 1) * TT + t) * VOCAB + j] = d1;
            logits[((size_t)(b0 + 2) * TT + t) * VOCAB + j] = d2;
            logits[((size_t)(b0 + 3) * TT + t) * VOCAB + j] = d3;
        }
        // note: no barrier needed here; next write to sH3 is behind 5 barriers
    }

    // ---- final hidden states: [NL, B, HID] ----
    if (tid < HID) {
#pragma unroll
        for (int r = 0; r < ROWS; r++) {
            hidden[(size_t)(0 * BB + b0 + r) * HID + tid] = s[OFF_H1 + r * HID + tid];
            hidden[(size_t)(1 * BB + b0 + r) * HID + tid] = s[OFF_H2 + r * HID + tid];
            hidden[(size_t)(2 * BB + b0 + r) * HID + tid] = s[OFF_H3 + r * HID + tid];
        }
    }
}

// ---------------------------------------------------------------------------
extern "C" void kernel_launch(void* const* d_in, const int* in_sizes, int n_in,
                              void* d_out, int out_size) {
    const int*   ids   = (const int*)  d_in[0];
    const float* emb   = (const float*)d_in[1];
    const float* W_ih  = (const float*)d_in[2];
    const float* W_hh  = (const float*)d_in[3];
    const float* b_ih  = (const float*)d_in[4];
    const float* b_hh  = (const float*)d_in[5];
    const float* W_dec = (const float*)d_in[6];
    const float* b_dec = (const float*)d_in[7];

    float* out    = (float*)d_out;
    float* logits = out;
    float* hidden = out + ((size_t)out_size - (size_t)NL * BB * HID);

    table_kernel<<<VOCAB, 128>>>(emb, W_ih, b_ih, b_hh);

    size_t smem = SMEM_FLOATS * sizeof(float);
    cudaFuncSetAttribute(rnn_kernel, cudaFuncAttributeMaxDynamicSharedMemorySize,
                         (int)smem);
    rnn_kernel<<<NCTA, NTHR, smem>>>(ids, W_ih, W_hh, b_ih, b_hh,
                                     W_dec, b_dec, logits, hidden);
}

// round 3
// speedup vs baseline: 1.3717x; 1.3717x over previous
#include <cuda_runtime.h>

// CharRNN: 3-layer tanh RNN, B=512, T=1024, HID=100, VOCAB=62.
// R3: 256 threads/CTA (8 warps), 2-way k-split with smem reduction,
//     packed fma.rn.f32x2 over k-pairs, biases in registers.

#define BB    512
#define TT    1024
#define HID   100
#define VOCAB 62
#define NL    3
#define ROWS  4
#define NCTA  (BB / ROWS)       // 128
#define NTHR  256

// ---- shared memory layout (floats) ----
#define OFF_WH1  0              // 100x100
#define OFF_WI2  10000
#define OFF_WH2  20000
#define OFF_WI3  30000
#define OFF_WH3  40000
#define OFF_WDEC 50000          // 62x100
#define OFF_H1   56200          // 4x100
#define OFF_H2   56600
#define OFF_H3   57000
#define OFF_SCR  57400          // 128 j * 4 floats (reduction scratch)
#define SMEM_FLOATS 57912       // 231,648 bytes (<= 232,448 max dyn smem)

__device__ float g_table[VOCAB * HID];  // emb@Wi1^T + b_ih1 + b_hh1

// ---------------------------------------------------------------------------
__global__ void table_kernel(const float* __restrict__ emb,
                             const float* __restrict__ W_ih,
                             const float* __restrict__ b_ih,
                             const float* __restrict__ b_hh) {
    int v = blockIdx.x;
    int j = threadIdx.x;
    if (j >= HID) return;
    float acc = b_ih[j] + b_hh[j];
    const float* e = emb + v * HID;
    const float* w = W_ih + j * HID;
#pragma unroll
    for (int k = 0; k < HID; k++) acc += e[k] * w[k];
    g_table[v * HID + j] = acc;
}

// ---------------------------------------------------------------------------
__device__ __forceinline__ void fma2(unsigned long long& acc,
                                     unsigned long long a,
                                     unsigned long long b) {
    asm("fma.rn.f32x2 %0, %1, %2, %3;" : "=l"(acc) : "l"(a), "l"(b), "l"(acc));
}
__device__ __forceinline__ float hadd2(unsigned long long a) {
    float lo = __uint_as_float((unsigned)a);
    float hi = __uint_as_float((unsigned)(a >> 32));
    return lo + hi;
}

// partial dot over chunks [KB,KE): acc[r] += w_row . h_row_r  (packed f32x2)
template <int KB, int KE>
__device__ __forceinline__ void dot1(const float* __restrict__ wrow,
                                     const float* __restrict__ hbase,
                                     unsigned long long acc[ROWS]) {
#pragma unroll
    for (int kc = KB; kc < KE; kc++) {
        ulonglong2 w = *reinterpret_cast<const ulonglong2*>(wrow + kc * 4);
#pragma unroll
        for (int r = 0; r < ROWS; r++) {
            ulonglong2 h = *reinterpret_cast<const ulonglong2*>(hbase + r * HID + kc * 4);
            fma2(acc[r], w.x, h.x);
            fma2(acc[r], w.y, h.y);
        }
    }
}

// two-matrix partial dot: acc[r] += wa . ha_r + wb . hb_r
template <int KB, int KE>
__device__ __forceinline__ void dot2(const float* __restrict__ warow,
                                     const float* __restrict__ wbrow,
                                     const float* __restrict__ habase,
                                     const float* __restrict__ hbbase,
                                     unsigned long long acc[ROWS]) {
#pragma unroll
    for (int kc = KB; kc < KE; kc++) {
        ulonglong2 wa = *reinterpret_cast<const ulonglong2*>(warow + kc * 4);
        ulonglong2 wb = *reinterpret_cast<const ulonglong2*>(wbrow + kc * 4);
#pragma unroll
        for (int r = 0; r < ROWS; r++) {
            ulonglong2 ha = *reinterpret_cast<const ulonglong2*>(habase + r * HID + kc * 4);
            ulonglong2 hb = *reinterpret_cast<const ulonglong2*>(hbbase + r * HID + kc * 4);
            fma2(acc[r], wa.x, ha.x);
            fma2(acc[r], wa.y, ha.y);
            fma2(acc[r], wb.x, hb.x);
            fma2(acc[r], wb.y, hb.y);
        }
    }
}

// ---------------------------------------------------------------------------
__global__ __launch_bounds__(NTHR, 1)
void rnn_kernel(const int*   __restrict__ ids,
                const float* __restrict__ W_ih,
                const float* __restrict__ W_hh,
                const float* __restrict__ b_ih,
                const float* __restrict__ b_hh,
                const float* __restrict__ W_dec,
                const float* __restrict__ b_dec,
                float* __restrict__ logits,
                float* __restrict__ hidden) {
    extern __shared__ float s[];
    const int tid = threadIdx.x;
    const int p   = tid >> 7;       // k-split group: 0 or 1
    const int j   = tid & 127;      // neuron index
    const int b0  = blockIdx.x * ROWS;

    // ---- stage weights into smem ----
    for (int i = tid; i < HID * HID; i += NTHR) {
        s[OFF_WH1 + i] = W_hh[i];
        s[OFF_WI2 + i] = W_ih[1 * HID * HID + i];
        s[OFF_WH2 + i] = W_hh[1 * HID * HID + i];
        s[OFF_WI3 + i] = W_ih[2 * HID * HID + i];
        s[OFF_WH3 + i] = W_hh[2 * HID * HID + i];
    }
    for (int i = tid; i < VOCAB * HID; i += NTHR) s[OFF_WDEC + i] = W_dec[i];
    for (int i = tid; i < ROWS * HID; i += NTHR) {
        s[OFF_H1 + i] = 0.0f;
        s[OFF_H2 + i] = 0.0f;
        s[OFF_H3 + i] = 0.0f;
    }
    // biases -> registers (only the reducer group p==0 needs them)
    float rb2 = 0.f, rb3 = 0.f, rbd = 0.f;
    if (p == 0 && j < HID) {
        rb2 = b_ih[1 * HID + j] + b_hh[1 * HID + j];
        rb3 = b_ih[2 * HID + j] + b_hh[2 * HID + j];
    }
    if (p == 0 && j < VOCAB) rbd = b_dec[j];
    __syncthreads();

    const float* wh1 = s + OFF_WH1 + j * HID;
    const float* wi2 = s + OFF_WI2 + j * HID;
    const float* wh2 = s + OFF_WH2 + j * HID;
    const float* wi3 = s + OFF_WI3 + j * HID;
    const float* wh3 = s + OFF_WH3 + j * HID;
    const float* wdc = s + OFF_WDEC + j * HID;

    for (int t = 0; t < TT; t++) {
        // ---- prefetch layer-1 token-table inputs (reducer group only) ----
        float tbl[ROWS];
        if (p == 0 && j < HID) {
#pragma unroll
            for (int r = 0; r < ROWS; r++) {
                int tok = ids[(b0 + r) * TT + t];
                tbl[r] = g_table[tok * HID + j];
            }
        }

        // ================= layer 1 =================
        {
            unsigned long long acc[ROWS] = {0ull, 0ull, 0ull, 0ull};
            if (j < HID) {
                if (p == 0) dot1<0, 13>(wh1, s + OFF_H1, acc);
                else        dot1<13, 25>(wh1, s + OFF_H1, acc);
            }
            float4 part;
            part.x = hadd2(acc[0]); part.y = hadd2(acc[1]);
            part.z = hadd2(acc[2]); part.w = hadd2(acc[3]);
            if (p == 1 && j < HID)
                *reinterpret_cast<float4*>(&s[OFF_SCR + 4 * j]) = part;
            __syncthreads();
            if (p == 0 && j < HID) {
                float4 o = *reinterpret_cast<const float4*>(&s[OFF_SCR + 4 * j]);
                s[OFF_H1 + 0 * HID + j] = tanhf(tbl[0] + part.x + o.x);
                s[OFF_H1 + 1 * HID + j] = tanhf(tbl[1] + part.y + o.y);
                s[OFF_H1 + 2 * HID + j] = tanhf(tbl[2] + part.z + o.z);
                s[OFF_H1 + 3 * HID + j] = tanhf(tbl[3] + part.w + o.w);
            }
            __syncthreads();
        }

        // ================= layer 2 =================
        {
            unsigned long long acc[ROWS] = {0ull, 0ull, 0ull, 0ull};
            if (j < HID) {
                if (p == 0) dot2<0, 13>(wi2, wh2, s + OFF_H1, s + OFF_H2, acc);
                else        dot2<13, 25>(wi2, wh2, s + OFF_H1, s + OFF_H2, acc);
            }
            float4 part;
            part.x = hadd2(acc[0]); part.y = hadd2(acc[1]);
            part.z = hadd2(acc[2]); part.w = hadd2(acc[3]);
            if (p == 1 && j < HID)
                *reinterpret_cast<float4*>(&s[OFF_SCR + 4 * j]) = part;
            __syncthreads();
            if (p == 0 && j < HID) {
                float4 o = *reinterpret_cast<const float4*>(&s[OFF_SCR + 4 * j]);
                s[OFF_H2 + 0 * HID + j] = tanhf(rb2 + part.x + o.x);
                s[OFF_H2 + 1 * HID + j] = tanhf(rb2 + part.y + o.y);
                s[OFF_H2 + 2 * HID + j] = tanhf(rb2 + part.z + o.z);
                s[OFF_H2 + 3 * HID + j] = tanhf(rb2 + part.w + o.w);
            }
            __syncthreads();
        }

        // ================= layer 3 =================
        {
            unsigned long long acc[ROWS] = {0ull, 0ull, 0ull, 0ull};
            if (j < HID) {
                if (p == 0) dot2<0, 13>(wi3, wh3, s + OFF_H2, s + OFF_H3, acc);
                else        dot2<13, 25>(wi3, wh3, s + OFF_H2, s + OFF_H3, acc);
            }
            float4 part;
            part.x = hadd2(acc[0]); part.y = hadd2(acc[1]);
            part.z = hadd2(acc[2]); part.w = hadd2(acc[3]);
            if (p == 1 && j < HID)
                *reinterpret_cast<float4*>(&s[OFF_SCR + 4 * j]) = part;
            __syncthreads();
            if (p == 0 && j < HID) {
                float4 o = *reinterpret_cast<const float4*>(&s[OFF_SCR + 4 * j]);
                s[OFF_H3 + 0 * HID + j] = tanhf(rb3 + part.x + o.x);
                s[OFF_H3 + 1 * HID + j] = tanhf(rb3 + part.y + o.y);
                s[OFF_H3 + 2 * HID + j] = tanhf(rb3 + part.z + o.z);
                s[OFF_H3 + 3 * HID + j] = tanhf(rb3 + part.w + o.w);
            }
            __syncthreads();
        }

        // ================= decoder =================
        {
            unsigned long long acc[ROWS] = {0ull, 0ull, 0ull, 0ull};
            if (j < VOCAB) {
                if (p == 0) dot1<0, 13>(wdc, s + OFF_H3, acc);
                else        dot1<13, 25>(wdc, s + OFF_H3, acc);
            }
            float4 part;
            part.x = hadd2(acc[0]); part.y = hadd2(acc[1]);
            part.z = hadd2(acc[2]); part.w = hadd2(acc[3]);
            if (p == 1 && j < VOCAB)
                *reinterpret_cast<float4*>(&s[OFF_SCR + 4 * j]) = part;
            __syncthreads();
            if (p == 0 && j < VOCAB) {
                float4 o = *reinterpret_cast<const float4*>(&s[OFF_SCR + 4 * j]);
                logits[((size_t)(b0 + 0) * TT + t) * VOCAB + j] = rbd + part.x + o.x;
                logits[((size_t)(b0 + 1) * TT + t) * VOCAB + j] = rbd + part.y + o.y;
                logits[((size_t)(b0 + 2) * TT + t) * VOCAB + j] = rbd + part.z + o.z;
                logits[((size_t)(b0 + 3) * TT + t) * VOCAB + j] = rbd + part.w + o.w;
            }
            __syncthreads();   // protect scratch before next step's layer-1 write
        }
    }

    // ---- final hidden states: [NL, B, HID] (values written by this thread) ----
    if (p == 0 && j < HID) {
#pragma unroll
        for (int r = 0; r < ROWS; r++) {
            hidden[(size_t)(0 * BB + b0 + r) * HID + j] = s[OFF_H1 + r * HID + j];
            hidden[(size_t)(1 * BB + b0 + r) * HID + j] = s[OFF_H2 + r * HID + j];
            hidden[(size_t)(2 * BB + b0 + r) * HID + j] = s[OFF_H3 + r * HID + j];
        }
    }
}

// ---------------------------------------------------------------------------
extern "C" void kernel_launch(void* const* d_in, const int* in_sizes, int n_in,
                              void* d_out, int out_size) {
    const int*   ids   = (const int*)  d_in[0];
    const float* emb   = (const float*)d_in[1];
    const float* W_ih  = (const float*)d_in[2];
    const float* W_hh  = (const float*)d_in[3];
    const float* b_ih  = (const float*)d_in[4];
    const float* b_hh  = (const float*)d_in[5];
    const float* W_dec = (const float*)d_in[6];
    const float* b_dec = (const float*)d_in[7];

    float* out    = (float*)d_out;
    float* logits = out;
    float* hidden = out + ((size_t)out_size - (size_t)NL * BB * HID);

    table_kernel<<<VOCAB, 128>>>(emb, W_ih, b_ih, b_hh);

    size_t smem = SMEM_FLOATS * sizeof(float);
    cudaFuncSetAttribute(rnn_kernel, cudaFuncAttributeMaxDynamicSharedMemorySize,
                         (int)smem);
    rnn_kernel<<<NCTA, NTHR, smem>>>(ids, W_ih, W_hh, b_ih, b_hh,
                                     W_dec, b_dec, logits, hidden);
}